// round 2
// baseline (speedup 1.0000x reference)
#include <cuda_runtime.h>

static constexpr int BB  = 256;
static constexpr int TT  = 256;
static constexpr int MM  = 8;
static constexpr int AUX = 32;
static constexpr int HH  = 64;
static constexpr int BT  = BB * TT;     // 65536
static constexpr int NC  = HH * HH;     // 4096

// Scratch (static device globals: allowed, no runtime allocation)
__device__ float g_r[(size_t)BT * NC];   // normalized softmax r, 1.07 GB
__device__ float g_min[(size_t)BT * HH]; // m_in, 16.8 MB

__device__ __forceinline__ void unpack2(unsigned long long v, float& lo, float& hi) {
    asm("mov.b64 {%0, %1}, %2;" : "=f"(lo), "=f"(hi) : "l"(v));
}
__device__ __forceinline__ void fma2(unsigned long long& d, unsigned long long a,
                                     unsigned long long b) {
    asm("fma.rn.f32x2 %0, %1, %2, %0;" : "+l"(d) : "l"(a), "l"(b));
}
__device__ __forceinline__ float rcp_fast(float x) {
    float r; asm("rcp.approx.ftz.f32 %0, %1;" : "=f"(r) : "f"(x)); return r;
}

// ---------------------------------------------------------------------------
// Phase 1: r[bt, h*64+k] = softmax_k( xa[bt,:] @ Wr[:, h*64+k] + br )
// Block tile: 64 bt-rows x 128 cols (= 2 full h-rows). 8 warps x 8 rows each.
// Lane l owns cols 4l..4l+3 (as 2 f32x2 accumulators per row).
// ---------------------------------------------------------------------------
__global__ __launch_bounds__(256) void k_phase1(const float* __restrict__ xa,
                                                const float* __restrict__ Wr,
                                                const float* __restrict__ br) {
    __shared__ __align__(16) float  sW[AUX][128];
    __shared__ __align__(16) float2 sX2[64][AUX];   // xa duplicated {x,x}

    const int cb  = blockIdx.x & 31;   // col block (128 cols)
    const int rb  = blockIdx.x >> 5;   // row block (64 rows)
    const int tid = threadIdx.x;

    for (int i4 = tid; i4 < 1024; i4 += 256) {      // Wr slab: 32 x 128 floats
        int a = i4 >> 5, c4 = i4 & 31;
        *(float4*)&sW[a][c4 * 4] =
            *(const float4*)(Wr + (size_t)a * NC + cb * 128 + c4 * 4);
    }
    {
        const float* gx = xa + (size_t)rb * 64 * AUX;
        float2* sx = &sX2[0][0];
        for (int i = tid; i < 64 * AUX; i += 256) {
            float v = gx[i];
            sx[i] = make_float2(v, v);
        }
    }
    __syncthreads();

    const int w = tid >> 5, l = tid & 31;
    const int r0 = w * 8;

    unsigned long long acc[8][2];
#pragma unroll
    for (int r = 0; r < 8; r++) { acc[r][0] = 0ull; acc[r][1] = 0ull; }

#pragma unroll 8
    for (int a = 0; a < AUX; a++) {
        ulonglong2 wv = *(const ulonglong2*)&sW[a][l * 4];
#pragma unroll
        for (int r = 0; r < 8; r++) {
            unsigned long long xx = *(const unsigned long long*)&sX2[r0 + r][a];
            fma2(acc[r][0], wv.x, xx);
            fma2(acc[r][1], wv.y, xx);
        }
    }

    float4 bias = *(const float4*)(br + cb * 128 + l * 4);
    size_t obase = ((size_t)(rb * 64 + r0)) * NC + cb * 128 + l * 4;
#pragma unroll
    for (int r = 0; r < 8; r++) {
        float v0, v1, v2, v3;
        unpack2(acc[r][0], v0, v1);
        unpack2(acc[r][1], v2, v3);
        v0 += bias.x; v1 += bias.y; v2 += bias.z; v3 += bias.w;
        // softmax over the 64-wide k row: lanes 0-15 hold h-even, 16-31 h-odd;
        // xor offsets <=8 stay inside each 16-lane group.
        float mx = fmaxf(fmaxf(v0, v1), fmaxf(v2, v3));
#pragma unroll
        for (int o = 8; o; o >>= 1) mx = fmaxf(mx, __shfl_xor_sync(0xffffffffu, mx, o));
        float e0 = __expf(v0 - mx), e1 = __expf(v1 - mx),
              e2 = __expf(v2 - mx), e3 = __expf(v3 - mx);
        float s = e0 + e1 + e2 + e3;
#pragma unroll
        for (int o = 8; o; o >>= 1) s += __shfl_xor_sync(0xffffffffu, s, o);
        float inv = rcp_fast(s);
        float4 ov = make_float4(e0 * inv, e1 * inv, e2 * inv, e3 * inv);
        *(float4*)(g_r + obase + (size_t)r * NC) = ov;
    }
}

// ---------------------------------------------------------------------------
// Phase 1b: m_in[bt,h] = sum_m xm[bt,m] * softmax_h( xa@Wj + bj )[m,h]
// Block: 16 bt-rows, 8 warps x 2 rows. 512 cols in two 256-col halves.
// ---------------------------------------------------------------------------
__global__ __launch_bounds__(256) void k_phase1b(const float* __restrict__ xa,
                                                 const float* __restrict__ xm,
                                                 const float* __restrict__ Wj,
                                                 const float* __restrict__ bj) {
    __shared__ __align__(16) float  sW[AUX][256];
    __shared__ __align__(16) float2 sX2[16][AUX];
    __shared__ float sM[16][MM];

    const int rb  = blockIdx.x;
    const int tid = threadIdx.x;
    const int w = tid >> 5, l = tid & 31;
    const int r0 = w * 2;

    {
        const float* gx = xa + (size_t)rb * 16 * AUX;
        float2* sx = &sX2[0][0];
        for (int i = tid; i < 16 * AUX; i += 256) {
            float v = gx[i];
            sx[i] = make_float2(v, v);
        }
        if (tid < 128) (&sM[0][0])[tid] = xm[(size_t)rb * 16 * MM + tid];
    }

    float pacc[2][4];
#pragma unroll
    for (int r = 0; r < 2; r++)
#pragma unroll
        for (int i = 0; i < 4; i++) pacc[r][i] = 0.f;

    for (int half = 0; half < 2; half++) {
        __syncthreads();
        for (int i4 = tid; i4 < 2048; i4 += 256) {   // Wj slab: 32 x 256 floats
            int a = i4 >> 6, c4 = i4 & 63;
            *(float4*)&sW[a][c4 * 4] =
                *(const float4*)(Wj + (size_t)a * (MM * HH) + half * 256 + c4 * 4);
        }
        __syncthreads();

        unsigned long long acc[2][2][2];
#pragma unroll
        for (int r = 0; r < 2; r++)
#pragma unroll
            for (int ch = 0; ch < 2; ch++) { acc[r][ch][0] = 0ull; acc[r][ch][1] = 0ull; }

#pragma unroll 8
        for (int a = 0; a < AUX; a++) {
            ulonglong2 w0 = *(const ulonglong2*)&sW[a][l * 4];
            ulonglong2 w1 = *(const ulonglong2*)&sW[a][128 + l * 4];
#pragma unroll
            for (int r = 0; r < 2; r++) {
                unsigned long long xx = *(const unsigned long long*)&sX2[r0 + r][a];
                fma2(acc[r][0][0], w0.x, xx);
                fma2(acc[r][0][1], w0.y, xx);
                fma2(acc[r][1][0], w1.x, xx);
                fma2(acc[r][1][1], w1.y, xx);
            }
        }

#pragma unroll
        for (int ch = 0; ch < 2; ch++) {
            float4 bias = *(const float4*)(bj + half * 256 + ch * 128 + l * 4);
            int m = half * 4 + ch * 2 + (l >> 4);
#pragma unroll
            for (int r = 0; r < 2; r++) {
                float v0, v1, v2, v3;
                unpack2(acc[r][ch][0], v0, v1);
                unpack2(acc[r][ch][1], v2, v3);
                v0 += bias.x; v1 += bias.y; v2 += bias.z; v3 += bias.w;
                float mx = fmaxf(fmaxf(v0, v1), fmaxf(v2, v3));
#pragma unroll
                for (int o = 8; o; o >>= 1)
                    mx = fmaxf(mx, __shfl_xor_sync(0xffffffffu, mx, o));
                float e0 = __expf(v0 - mx), e1 = __expf(v1 - mx),
                      e2 = __expf(v2 - mx), e3 = __expf(v3 - mx);
                float s = e0 + e1 + e2 + e3;
#pragma unroll
                for (int o = 8; o; o >>= 1)
                    s += __shfl_xor_sync(0xffffffffu, s, o);
                float f = sM[r0 + r][m] * rcp_fast(s);
                pacc[r][0] += e0 * f; pacc[r][1] += e1 * f;
                pacc[r][2] += e2 * f; pacc[r][3] += e3 * f;
            }
        }
    }

    // combine the two m-parities (lanes l and l^16 hold the same h group)
#pragma unroll
    for (int r = 0; r < 2; r++) {
        float4 v = make_float4(pacc[r][0], pacc[r][1], pacc[r][2], pacc[r][3]);
        v.x += __shfl_xor_sync(0xffffffffu, v.x, 16);
        v.y += __shfl_xor_sync(0xffffffffu, v.y, 16);
        v.z += __shfl_xor_sync(0xffffffffu, v.z, 16);
        v.w += __shfl_xor_sync(0xffffffffu, v.w, 16);
        if (l < 16)
            *(float4*)(g_min + (size_t)(rb * 16 + r0 + r) * HH + l * 4) = v;
    }
}

// ---------------------------------------------------------------------------
// Phase 2: per-batch sequential scan. c_t[k] = m_in[k] + sum_h c[h]*r[t,h,k].
// 256 blocks (one per b), 256 threads = 4 h-groups x 64 k. 1-step prefetch.
// Tail: out[b] = (sigmoid(xa_{T-1}@Wo+bo) * c_T) @ Wfc + bfc; also c_final.
// ---------------------------------------------------------------------------
__global__ __launch_bounds__(256) void k_phase2(const float* __restrict__ xa,
                                                const float* __restrict__ Wo,
                                                const float* __restrict__ bo,
                                                const float* __restrict__ Wfc,
                                                const float* __restrict__ bfc,
                                                float* __restrict__ out) {
    const int b = blockIdx.x;
    const int tid = threadIdx.x;
    const int g = tid >> 6, k = tid & 63;
    __shared__ float sc[HH];
    __shared__ float sp[4][HH];
    if (tid < HH) sc[tid] = 0.f;
    __syncthreads();

    const float* rb_ = g_r + (size_t)b * TT * NC;
    const float* mb  = g_min + (size_t)b * TT * HH;

    float rv[16];
#pragma unroll
    for (int i = 0; i < 16; i++) rv[i] = rb_[(g * 16 + i) * HH + k];
    float mn = mb[k];

    for (int t = 0; t < TT; t++) {
        const int tn = (t + 1 < TT) ? t + 1 : t;
        const float* rp = rb_ + (size_t)tn * NC;
        float rn[16];
#pragma unroll
        for (int i = 0; i < 16; i++) rn[i] = rp[(g * 16 + i) * HH + k];
        float mnext = mb[tn * HH + k];

        float p = 0.f;
#pragma unroll
        for (int i = 0; i < 16; i++) p += sc[g * 16 + i] * rv[i];
        sp[g][k] = p;
        __syncthreads();
        if (g == 0) sc[k] = mn + sp[0][k] + sp[1][k] + sp[2][k] + sp[3][k];
        __syncthreads();
#pragma unroll
        for (int i = 0; i < 16; i++) rv[i] = rn[i];
        mn = mnext;
    }

    if (g == 0) {
        const float* xarow = xa + ((size_t)b * TT + (TT - 1)) * AUX;
        float acc = bo[k];
#pragma unroll
        for (int a = 0; a < AUX; a++) acc = fmaf(xarow[a], Wo[a * HH + k], acc);
        float o = 1.f / (1.f + __expf(-acc));
        float cfin = sc[k];
        out[BB + b * HH + k] = cfin;           // c_final at offset 256
        sp[0][k] = o * cfin * Wfc[k];
    }
    __syncthreads();
    if (tid == 0) {
        float s = bfc[0];
        for (int i = 0; i < HH; i++) s += sp[0][i];
        out[b] = s;                            // out[b, 0]
    }
}

extern "C" void kernel_launch(void* const* d_in, const int* in_sizes, int n_in,
                              void* d_out, int out_size) {
    const float* xm  = (const float*)d_in[0];
    const float* xa  = (const float*)d_in[1];
    const float* Wj  = (const float*)d_in[2];
    const float* bj  = (const float*)d_in[3];
    const float* Wr  = (const float*)d_in[4];
    const float* br  = (const float*)d_in[5];
    const float* Wo  = (const float*)d_in[6];
    const float* bo  = (const float*)d_in[7];
    const float* Wfc = (const float*)d_in[8];
    const float* bfc = (const float*)d_in[9];
    float* out = (float*)d_out;

    k_phase1<<<(BT / 64) * (NC / 128), 256>>>(xa, Wr, br);   // 32768 blocks
    k_phase1b<<<BT / 16, 256>>>(xa, xm, Wj, bj);             // 4096 blocks
    k_phase2<<<BB, 256>>>(xa, Wo, bo, Wfc, bfc, out);        // 256 blocks
}

// round 3
// speedup vs baseline: 1.0213x; 1.0213x over previous
#include <cuda_runtime.h>
#include <cuda_fp16.h>

static constexpr int BB  = 256;
static constexpr int TT  = 256;
static constexpr int MM  = 8;
static constexpr int AUX = 32;
static constexpr int HH  = 64;
static constexpr int BT  = BB * TT;     // 65536
static constexpr int NC  = HH * HH;     // 4096

// Scratch (static device globals: allowed, no runtime allocation)
__device__ __half g_r[(size_t)BT * NC];   // normalized softmax r, fp16, 537 MB
__device__ float  g_min[(size_t)BT * HH]; // m_in, fp32, 16.8 MB

__device__ __forceinline__ void unpack2(unsigned long long v, float& lo, float& hi) {
    asm("mov.b64 {%0, %1}, %2;" : "=f"(lo), "=f"(hi) : "l"(v));
}
__device__ __forceinline__ void fma2(unsigned long long& d, unsigned long long a,
                                     unsigned long long b) {
    asm("fma.rn.f32x2 %0, %1, %2, %0;" : "+l"(d) : "l"(a), "l"(b));
}
__device__ __forceinline__ float rcp_fast(float x) {
    float r; asm("rcp.approx.ftz.f32 %0, %1;" : "=f"(r) : "f"(x)); return r;
}

// ---------------------------------------------------------------------------
// Phase 1: r[bt, h*64+k] = softmax_k( xa[bt,:] @ Wr[:, h*64+k] + br ), fp16 out
// Tile: 64 bt-rows x 256 cols. 8 warps x 8 rows; lane owns 8 cols (4 f32x2 acc
// per row). Softmax over 8-lane groups (one h each), xor 4/2/1.
// smem: sW 32x256 f32 (32KB) + sX2 64x32 float2 dup (16KB) = 48KB dynamic.
// ---------------------------------------------------------------------------
__global__ __launch_bounds__(256) void k_phase1(const float* __restrict__ xa,
                                                const float* __restrict__ Wr,
                                                const float* __restrict__ br) {
    extern __shared__ __align__(16) char smem[];
    float*  sW  = (float*)smem;                 // [32][256]
    float2* sX2 = (float2*)(smem + 32768);      // [64][32]

    const int cb  = blockIdx.x & 15;   // col block (256 cols)
    const int rb  = blockIdx.x >> 4;   // row block (64 rows)
    const int tid = threadIdx.x;

    for (int i4 = tid; i4 < 2048; i4 += 256) {  // Wr slab: 32 x 256 floats
        int a = i4 >> 6, c4 = i4 & 63;
        *(float4*)&sW[a * 256 + c4 * 4] =
            *(const float4*)(Wr + (size_t)a * NC + cb * 256 + c4 * 4);
    }
    {
        const float* gx = xa + (size_t)rb * 64 * AUX;
        for (int i = tid; i < 64 * AUX; i += 256) {
            float v = gx[i];
            sX2[i] = make_float2(v, v);
        }
    }
    __syncthreads();

    const int w = tid >> 5, l = tid & 31;
    const int r0 = w * 8;

    unsigned long long acc[8][4];
#pragma unroll
    for (int r = 0; r < 8; r++)
#pragma unroll
        for (int j = 0; j < 4; j++) acc[r][j] = 0ull;

#pragma unroll 4
    for (int a = 0; a < AUX; a++) {
        ulonglong2 w0 = *(const ulonglong2*)&sW[a * 256 + l * 8];
        ulonglong2 w1 = *(const ulonglong2*)&sW[a * 256 + l * 8 + 4];
#pragma unroll
        for (int r = 0; r < 8; r++) {
            unsigned long long xx = *(const unsigned long long*)&sX2[(r0 + r) * AUX + a];
            fma2(acc[r][0], w0.x, xx);
            fma2(acc[r][1], w0.y, xx);
            fma2(acc[r][2], w1.x, xx);
            fma2(acc[r][3], w1.y, xx);
        }
    }

    float4 b0 = *(const float4*)(br + cb * 256 + l * 8);
    float4 b1 = *(const float4*)(br + cb * 256 + l * 8 + 4);
    __half* op = g_r + (size_t)(rb * 64 + r0) * NC + cb * 256 + l * 8;
#pragma unroll
    for (int r = 0; r < 8; r++) {
        float v[8];
        unpack2(acc[r][0], v[0], v[1]);
        unpack2(acc[r][1], v[2], v[3]);
        unpack2(acc[r][2], v[4], v[5]);
        unpack2(acc[r][3], v[6], v[7]);
        v[0] += b0.x; v[1] += b0.y; v[2] += b0.z; v[3] += b0.w;
        v[4] += b1.x; v[5] += b1.y; v[6] += b1.z; v[7] += b1.w;
        float mx = v[0];
#pragma unroll
        for (int j = 1; j < 8; j++) mx = fmaxf(mx, v[j]);
#pragma unroll
        for (int o = 4; o; o >>= 1) mx = fmaxf(mx, __shfl_xor_sync(0xffffffffu, mx, o));
        float e[8], s = 0.f;
#pragma unroll
        for (int j = 0; j < 8; j++) { e[j] = __expf(v[j] - mx); s += e[j]; }
#pragma unroll
        for (int o = 4; o; o >>= 1) s += __shfl_xor_sync(0xffffffffu, s, o);
        float inv = rcp_fast(s);
        __half2 hh[4];
#pragma unroll
        for (int j = 0; j < 4; j++)
            hh[j] = __floats2half2_rn(e[2 * j] * inv, e[2 * j + 1] * inv);
        *(uint4*)(op + (size_t)r * NC) = *(uint4*)hh;
    }
}

// ---------------------------------------------------------------------------
// Phase 1b: m_in[bt,h] = sum_m xm[bt,m] * softmax_h( xa@Wj + bj )[m,h]
// Same inner as phase1: 64 rows, 8 warps x 8 rows, C=8, two 256-col halves.
// m-reduction: shuffle xor 8/16 across the 4 m-groups, accumulate in sMin.
// smem: sW 32KB + sX2 16KB + sM 2KB + sMin 16KB = 66KB dynamic.
// ---------------------------------------------------------------------------
__global__ __launch_bounds__(256) void k_phase1b(const float* __restrict__ xa,
                                                 const float* __restrict__ xm,
                                                 const float* __restrict__ Wj,
                                                 const float* __restrict__ bj) {
    extern __shared__ __align__(16) char smem[];
    float*  sW   = (float*)smem;                       // [32][256]
    float2* sX2  = (float2*)(smem + 32768);            // [64][32]
    float*  sM   = (float*)(smem + 32768 + 16384);     // [64][8]
    float*  sMin = (float*)(smem + 32768 + 16384 + 2048); // [64][64]

    const int rb  = blockIdx.x;
    const int tid = threadIdx.x;
    const int w = tid >> 5, l = tid & 31;
    const int r0 = w * 8;

    {
        const float* gx = xa + (size_t)rb * 64 * AUX;
        for (int i = tid; i < 64 * AUX; i += 256) {
            float v = gx[i];
            sX2[i] = make_float2(v, v);
        }
        for (int i = tid; i < 64 * MM; i += 256)
            sM[i] = xm[(size_t)rb * 64 * MM + i];
    }

    for (int half = 0; half < 2; half++) {
        __syncthreads();
        for (int i4 = tid; i4 < 2048; i4 += 256) {   // Wj slab: 32 x 256 floats
            int a = i4 >> 6, c4 = i4 & 63;
            *(float4*)&sW[a * 256 + c4 * 4] =
                *(const float4*)(Wj + (size_t)a * (MM * HH) + half * 256 + c4 * 4);
        }
        __syncthreads();

        unsigned long long acc[8][4];
#pragma unroll
        for (int r = 0; r < 8; r++)
#pragma unroll
            for (int j = 0; j < 4; j++) acc[r][j] = 0ull;

#pragma unroll 4
        for (int a = 0; a < AUX; a++) {
            ulonglong2 w0 = *(const ulonglong2*)&sW[a * 256 + l * 8];
            ulonglong2 w1 = *(const ulonglong2*)&sW[a * 256 + l * 8 + 4];
#pragma unroll
            for (int r = 0; r < 8; r++) {
                unsigned long long xx = *(const unsigned long long*)&sX2[(r0 + r) * AUX + a];
                fma2(acc[r][0], w0.x, xx);
                fma2(acc[r][1], w0.y, xx);
                fma2(acc[r][2], w1.x, xx);
                fma2(acc[r][3], w1.y, xx);
            }
        }

        float4 b0 = *(const float4*)(bj + half * 256 + l * 8);
        float4 b1 = *(const float4*)(bj + half * 256 + l * 8 + 4);
        const int m = half * 4 + (l >> 3);
#pragma unroll
        for (int r = 0; r < 8; r++) {
            float v[8];
            unpack2(acc[r][0], v[0], v[1]);
            unpack2(acc[r][1], v[2], v[3]);
            unpack2(acc[r][2], v[4], v[5]);
            unpack2(acc[r][3], v[6], v[7]);
            v[0] += b0.x; v[1] += b0.y; v[2] += b0.z; v[3] += b0.w;
            v[4] += b1.x; v[5] += b1.y; v[6] += b1.z; v[7] += b1.w;
            float mx = v[0];
#pragma unroll
            for (int j = 1; j < 8; j++) mx = fmaxf(mx, v[j]);
#pragma unroll
            for (int o = 4; o; o >>= 1)
                mx = fmaxf(mx, __shfl_xor_sync(0xffffffffu, mx, o));
            float e[8], s = 0.f;
#pragma unroll
            for (int j = 0; j < 8; j++) { e[j] = __expf(v[j] - mx); s += e[j]; }
#pragma unroll
            for (int o = 4; o; o >>= 1)
                s += __shfl_xor_sync(0xffffffffu, s, o);
            float f = sM[(r0 + r) * MM + m] * rcp_fast(s);
            float c[8];
#pragma unroll
            for (int j = 0; j < 8; j++) c[j] = e[j] * f;
            // reduce over the 4 m-groups within the warp (lanes xor 8, 16)
#pragma unroll
            for (int j = 0; j < 8; j++) {
                c[j] += __shfl_xor_sync(0xffffffffu, c[j], 8);
                c[j] += __shfl_xor_sync(0xffffffffu, c[j], 16);
            }
            if (l < 8) {
                float* dst = &sMin[(r0 + r) * HH + l * 8];
                if (half == 0) {
#pragma unroll
                    for (int j = 0; j < 8; j++) dst[j] = c[j];
                } else {
#pragma unroll
                    for (int j = 0; j < 8; j++) dst[j] += c[j];
                }
            }
        }
    }
    __syncthreads();
    {
        float4* go = (float4*)(g_min + (size_t)rb * 64 * HH);
        const float4* si = (const float4*)sMin;
        for (int i = tid; i < 1024; i += 256) go[i] = si[i];
    }
}

// ---------------------------------------------------------------------------
// Phase 2: per-batch sequential scan, fp16 r.
// 256 blocks (one per b), 128 threads: g = tid>>4 (8 h per group),
// k4 = tid&15 (4 k each). Per step: 8 x LDG.64 (4 halves), 32 fp32 MACs,
// partials to sp[8][64], 64 reducer threads form c. 1-step register prefetch.
// Tail: out[b] = (sigmoid(xa_{T-1}@Wo+bo) * c_T) @ Wfc + bfc; c_final stored.
// ---------------------------------------------------------------------------
__global__ __launch_bounds__(128) void k_phase2(const float* __restrict__ xa,
                                                const float* __restrict__ Wo,
                                                const float* __restrict__ bo,
                                                const float* __restrict__ Wfc,
                                                const float* __restrict__ bfc,
                                                float* __restrict__ out) {
    const int b = blockIdx.x;
    const int tid = threadIdx.x;
    const int g = tid >> 4, k4 = tid & 15;
    __shared__ float sc[HH];
    __shared__ float sp[8][HH];
    if (tid < HH) sc[tid] = 0.f;
    __syncthreads();

    const __half* rb_ = g_r + (size_t)b * TT * NC;
    const float*  mb  = g_min + (size_t)b * TT * HH;
    const __half* p0  = rb_ + (g * 8) * HH + k4 * 4;

    uint2 rv[8];
#pragma unroll
    for (int i = 0; i < 8; i++) rv[i] = *(const uint2*)(p0 + i * HH);
    float mn = (tid < HH) ? mb[tid] : 0.f;

    for (int t = 0; t < TT; t++) {
        const int tn = (t + 1 < TT) ? t + 1 : t;
        const __half* pn = rb_ + (size_t)tn * NC + (g * 8) * HH + k4 * 4;
        uint2 rn[8];
#pragma unroll
        for (int i = 0; i < 8; i++) rn[i] = *(const uint2*)(pn + i * HH);
        float mnext = (tid < HH) ? mb[tn * HH + tid] : 0.f;

        float4 p = make_float4(0.f, 0.f, 0.f, 0.f);
#pragma unroll
        for (int i = 0; i < 8; i++) {
            float c = sc[g * 8 + i];
            __half2 h01 = *(__half2*)&rv[i].x;
            __half2 h23 = *(__half2*)&rv[i].y;
            float2 f01 = __half22float2(h01);
            float2 f23 = __half22float2(h23);
            p.x = fmaf(c, f01.x, p.x);
            p.y = fmaf(c, f01.y, p.y);
            p.z = fmaf(c, f23.x, p.z);
            p.w = fmaf(c, f23.y, p.w);
        }
        *(float4*)&sp[g][k4 * 4] = p;
        __syncthreads();
        if (tid < HH) {
            float v = mn;
#pragma unroll
            for (int gg = 0; gg < 8; gg++) v += sp[gg][tid];
            sc[tid] = v;
        }
        __syncthreads();
#pragma unroll
        for (int i = 0; i < 8; i++) rv[i] = rn[i];
        mn = mnext;
    }

    if (tid < HH) {
        const int k = tid;
        const float* xarow = xa + ((size_t)b * TT + (TT - 1)) * AUX;
        float acc = bo[k];
#pragma unroll
        for (int a = 0; a < AUX; a++) acc = fmaf(xarow[a], Wo[a * HH + k], acc);
        float o = 1.f / (1.f + __expf(-acc));
        float cfin = sc[k];
        out[BB + b * HH + k] = cfin;           // c_final at offset 256
        sp[0][k] = o * cfin * Wfc[k];
    }
    __syncthreads();
    if (tid == 0) {
        float s = bfc[0];
        for (int i = 0; i < HH; i++) s += sp[0][i];
        out[b] = s;                            // out[b, 0]
    }
}

extern "C" void kernel_launch(void* const* d_in, const int* in_sizes, int n_in,
                              void* d_out, int out_size) {
    const float* xm  = (const float*)d_in[0];
    const float* xa  = (const float*)d_in[1];
    const float* Wj  = (const float*)d_in[2];
    const float* bj  = (const float*)d_in[3];
    const float* Wr  = (const float*)d_in[4];
    const float* br  = (const float*)d_in[5];
    const float* Wo  = (const float*)d_in[6];
    const float* bo  = (const float*)d_in[7];
    const float* Wfc = (const float*)d_in[8];
    const float* bfc = (const float*)d_in[9];
    float* out = (float*)d_out;

    static bool attr_done = false;
    if (!attr_done) {
        cudaFuncSetAttribute(k_phase1,  cudaFuncAttributeMaxDynamicSharedMemorySize, 49152);
        cudaFuncSetAttribute(k_phase1b, cudaFuncAttributeMaxDynamicSharedMemorySize, 67584);
        attr_done = true;
    }

    k_phase1 <<<(BT / 64) * (NC / 256), 256, 49152>>>(xa, Wr, br);   // 16384 blocks
    k_phase1b<<<BT / 64, 256, 67584>>>(xa, xm, Wj, bj);              // 1024 blocks
    k_phase2 <<<BB, 128>>>(xa, Wo, bo, Wfc, bfc, out);               // 256 blocks
}

// round 4
// speedup vs baseline: 1.7473x; 1.7109x over previous
#include <cuda_runtime.h>
#include <cuda_fp16.h>

static constexpr int BB  = 256;
static constexpr int TT  = 256;
static constexpr int MM  = 8;
static constexpr int AUX = 32;
static constexpr int HH  = 64;
static constexpr int BT  = BB * TT;     // 65536
static constexpr int NC  = HH * HH;     // 4096

// Scratch (static device globals: allowed, no runtime allocation)
__device__ __half g_r[(size_t)BT * NC];     // normalized softmax r, fp16, 537 MB
__device__ float  g_min[(size_t)BT * HH];   // m_in, fp32, 16.8 MB
__device__ __half g_xa_h[(size_t)BT * AUX]; // xa in fp16
__device__ __half g_wT[(size_t)NC * AUX];   // Wr transposed [n=4096][k=32] fp16

__device__ __forceinline__ void unpack2(unsigned long long v, float& lo, float& hi) {
    asm("mov.b64 {%0, %1}, %2;" : "=f"(lo), "=f"(hi) : "l"(v));
}
__device__ __forceinline__ void fma2(unsigned long long& d, unsigned long long a,
                                     unsigned long long b) {
    asm("fma.rn.f32x2 %0, %1, %2, %0;" : "+l"(d) : "l"(a), "l"(b));
}
__device__ __forceinline__ float rcp_fast(float x) {
    float r; asm("rcp.approx.ftz.f32 %0, %1;" : "=f"(r) : "f"(x)); return r;
}
__device__ __forceinline__ void mma16816(float4& d, unsigned a0, unsigned a1,
                                         unsigned a2, unsigned a3,
                                         unsigned b0, unsigned b1) {
    asm volatile(
        "mma.sync.aligned.m16n8k16.row.col.f32.f16.f16.f32 "
        "{%0,%1,%2,%3}, {%4,%5,%6,%7}, {%8,%9}, {%0,%1,%2,%3};"
        : "+f"(d.x), "+f"(d.y), "+f"(d.z), "+f"(d.w)
        : "r"(a0), "r"(a1), "r"(a2), "r"(a3), "r"(b0), "r"(b1));
}

// ---------------------------------------------------------------------------
// Converters (run every launch; deterministic)
// ---------------------------------------------------------------------------
__global__ __launch_bounds__(256) void k_cvt_xa(const float* __restrict__ xa) {
    int i = blockIdx.x * 256 + threadIdx.x;           // 524288 total (x4 elems)
    float4 v = ((const float4*)xa)[i];
    __half2 h01 = __floats2half2_rn(v.x, v.y);
    __half2 h23 = __floats2half2_rn(v.z, v.w);
    uint2 o; o.x = *(unsigned*)&h01; o.y = *(unsigned*)&h23;
    ((uint2*)g_xa_h)[i] = o;
}
__global__ __launch_bounds__(256) void k_cvt_w(const float* __restrict__ Wr) {
    int i = blockIdx.x * 256 + threadIdx.x;           // 131072 total
    int k = i >> 12, n = i & 4095;
    g_wT[n * AUX + k] = __float2half(Wr[i]);
}

// ---------------------------------------------------------------------------
// Phase 1 (tensor-core): logits = xa_h @ Wr_h, softmax over 64-col groups,
// store fp16. Block = 256 thr = 8 warps (2m x 4n), tile 32 rows x 256 cols.
// Grid: 2048 row-blocks x 16 col-blocks.
// ---------------------------------------------------------------------------
__global__ __launch_bounds__(256) void k_phase1(const float* __restrict__ br) {
    __shared__ __align__(16) __half sA[32 * 40];       // rows pad 40
    __shared__ __align__(16) __half sB[256 * 40];      // [n][k] pad 40
    __shared__ __align__(16) float  sBias[256];
    __shared__ __align__(16) __half sOut[32 * 264];    // rows pad 264

    const int cb  = blockIdx.x & 15;
    const int rb  = blockIdx.x >> 4;
    const int tid = threadIdx.x;

    // load A (32 x 32 halves)
    if (tid < 128) {
        int row = tid >> 2, q = tid & 3;
        *(uint4*)(sA + row * 40 + q * 8) =
            *(const uint4*)(g_xa_h + (size_t)(rb * 32) * AUX + row * AUX + q * 8);
    }
    // load B (256 x 32 halves)
    for (int i = tid; i < 1024; i += 256) {
        int n = i >> 2, q = i & 3;
        *(uint4*)(sB + n * 40 + q * 8) =
            *(const uint4*)(g_wT + (size_t)(cb * 256 + n) * AUX + q * 8);
    }
    if (tid < 64) ((float4*)sBias)[tid] = ((const float4*)(br + cb * 256))[tid];
    __syncthreads();

    const int warp = tid >> 5, lane = tid & 31;
    const int g = lane >> 2, t2 = (lane & 3) * 2;
    const int wm = (warp >> 2) * 16;     // 0 / 16
    const int wn = (warp & 3) * 64;      // h-group base

    float4 d[8];
#pragma unroll
    for (int t = 0; t < 8; t++) d[t] = make_float4(0.f, 0.f, 0.f, 0.f);

#pragma unroll
    for (int ks = 0; ks < 2; ks++) {
        const __half* Ab = sA + wm * 40 + ks * 16;
        unsigned a0 = *(const unsigned*)(Ab + g * 40 + t2);
        unsigned a1 = *(const unsigned*)(Ab + (g + 8) * 40 + t2);
        unsigned a2 = *(const unsigned*)(Ab + g * 40 + t2 + 8);
        unsigned a3 = *(const unsigned*)(Ab + (g + 8) * 40 + t2 + 8);
#pragma unroll
        for (int t = 0; t < 8; t++) {
            const __half* Bp = sB + (wn + t * 8 + g) * 40 + ks * 16;
            unsigned b0 = *(const unsigned*)(Bp + t2);
            unsigned b1 = *(const unsigned*)(Bp + t2 + 8);
            mma16816(d[t], a0, a1, a2, a3, b0, b1);
        }
    }

    // epilogue: softmax over the 64 cols of this warp's h-group, two rows.
    float v0[16], v1[16];
#pragma unroll
    for (int t = 0; t < 8; t++) {
        float bx = sBias[wn + t * 8 + t2], by = sBias[wn + t * 8 + t2 + 1];
        v0[2 * t]     = d[t].x + bx; v0[2 * t + 1] = d[t].y + by;
        v1[2 * t]     = d[t].z + bx; v1[2 * t + 1] = d[t].w + by;
    }
    float mx0 = v0[0], mx1 = v1[0];
#pragma unroll
    for (int j = 1; j < 16; j++) { mx0 = fmaxf(mx0, v0[j]); mx1 = fmaxf(mx1, v1[j]); }
#pragma unroll
    for (int o = 2; o; o >>= 1) {
        mx0 = fmaxf(mx0, __shfl_xor_sync(0xffffffffu, mx0, o));
        mx1 = fmaxf(mx1, __shfl_xor_sync(0xffffffffu, mx1, o));
    }
    float s0 = 0.f, s1 = 0.f;
#pragma unroll
    for (int j = 0; j < 16; j++) {
        v0[j] = __expf(v0[j] - mx0); s0 += v0[j];
        v1[j] = __expf(v1[j] - mx1); s1 += v1[j];
    }
#pragma unroll
    for (int o = 2; o; o >>= 1) {
        s0 += __shfl_xor_sync(0xffffffffu, s0, o);
        s1 += __shfl_xor_sync(0xffffffffu, s1, o);
    }
    float inv0 = rcp_fast(s0), inv1 = rcp_fast(s1);
#pragma unroll
    for (int t = 0; t < 8; t++) {
        __half2 h0 = __floats2half2_rn(v0[2 * t] * inv0, v0[2 * t + 1] * inv0);
        __half2 h1 = __floats2half2_rn(v1[2 * t] * inv1, v1[2 * t + 1] * inv1);
        *(__half2*)(sOut + (wm + g) * 264 + wn + t * 8 + t2)     = h0;
        *(__half2*)(sOut + (wm + g + 8) * 264 + wn + t * 8 + t2) = h1;
    }
    __syncthreads();

    // coalesced copy out: 32 rows x 256 halves
    for (int i = tid; i < 1024; i += 256) {
        int row = i >> 5, q = i & 31;
        *(uint4*)(g_r + (size_t)(rb * 32 + row) * NC + cb * 256 + q * 8) =
            *(const uint4*)(sOut + row * 264 + q * 8);
    }
}

// ---------------------------------------------------------------------------
// Phase 1b: m_in[bt,h] = sum_m xm[bt,m] * softmax_h( xa@Wj + bj )[m,h]
// (unchanged from round 2 — passed)
// ---------------------------------------------------------------------------
__global__ __launch_bounds__(256) void k_phase1b(const float* __restrict__ xa,
                                                 const float* __restrict__ xm,
                                                 const float* __restrict__ Wj,
                                                 const float* __restrict__ bj) {
    extern __shared__ __align__(16) char smem[];
    float*  sW   = (float*)smem;                       // [32][256]
    float2* sX2  = (float2*)(smem + 32768);            // [64][32]
    float*  sM   = (float*)(smem + 32768 + 16384);     // [64][8]
    float*  sMin = (float*)(smem + 32768 + 16384 + 2048); // [64][64]

    const int rb  = blockIdx.x;
    const int tid = threadIdx.x;
    const int w = tid >> 5, l = tid & 31;
    const int r0 = w * 8;

    {
        const float* gx = xa + (size_t)rb * 64 * AUX;
        for (int i = tid; i < 64 * AUX; i += 256) {
            float v = gx[i];
            sX2[i] = make_float2(v, v);
        }
        for (int i = tid; i < 64 * MM; i += 256)
            sM[i] = xm[(size_t)rb * 64 * MM + i];
    }

    for (int half = 0; half < 2; half++) {
        __syncthreads();
        for (int i4 = tid; i4 < 2048; i4 += 256) {
            int a = i4 >> 6, c4 = i4 & 63;
            *(float4*)&sW[a * 256 + c4 * 4] =
                *(const float4*)(Wj + (size_t)a * (MM * HH) + half * 256 + c4 * 4);
        }
        __syncthreads();

        unsigned long long acc[8][4];
#pragma unroll
        for (int r = 0; r < 8; r++)
#pragma unroll
            for (int j = 0; j < 4; j++) acc[r][j] = 0ull;

#pragma unroll 4
        for (int a = 0; a < AUX; a++) {
            ulonglong2 w0 = *(const ulonglong2*)&sW[a * 256 + l * 8];
            ulonglong2 w1 = *(const ulonglong2*)&sW[a * 256 + l * 8 + 4];
#pragma unroll
            for (int r = 0; r < 8; r++) {
                unsigned long long xx = *(const unsigned long long*)&sX2[(r0 + r) * AUX + a];
                fma2(acc[r][0], w0.x, xx);
                fma2(acc[r][1], w0.y, xx);
                fma2(acc[r][2], w1.x, xx);
                fma2(acc[r][3], w1.y, xx);
            }
        }

        float4 b0 = *(const float4*)(bj + half * 256 + l * 8);
        float4 b1 = *(const float4*)(bj + half * 256 + l * 8 + 4);
        const int m = half * 4 + (l >> 3);
#pragma unroll
        for (int r = 0; r < 8; r++) {
            float v[8];
            unpack2(acc[r][0], v[0], v[1]);
            unpack2(acc[r][1], v[2], v[3]);
            unpack2(acc[r][2], v[4], v[5]);
            unpack2(acc[r][3], v[6], v[7]);
            v[0] += b0.x; v[1] += b0.y; v[2] += b0.z; v[3] += b0.w;
            v[4] += b1.x; v[5] += b1.y; v[6] += b1.z; v[7] += b1.w;
            float mx = v[0];
#pragma unroll
            for (int j = 1; j < 8; j++) mx = fmaxf(mx, v[j]);
#pragma unroll
            for (int o = 4; o; o >>= 1)
                mx = fmaxf(mx, __shfl_xor_sync(0xffffffffu, mx, o));
            float e[8], s = 0.f;
#pragma unroll
            for (int j = 0; j < 8; j++) { e[j] = __expf(v[j] - mx); s += e[j]; }
#pragma unroll
            for (int o = 4; o; o >>= 1)
                s += __shfl_xor_sync(0xffffffffu, s, o);
            float f = sM[(r0 + r) * MM + m] * rcp_fast(s);
            float c[8];
#pragma unroll
            for (int j = 0; j < 8; j++) c[j] = e[j] * f;
#pragma unroll
            for (int j = 0; j < 8; j++) {
                c[j] += __shfl_xor_sync(0xffffffffu, c[j], 8);
                c[j] += __shfl_xor_sync(0xffffffffu, c[j], 16);
            }
            if (l < 8) {
                float* dst = &sMin[(r0 + r) * HH + l * 8];
                if (half == 0) {
#pragma unroll
                    for (int j = 0; j < 8; j++) dst[j] = c[j];
                } else {
#pragma unroll
                    for (int j = 0; j < 8; j++) dst[j] += c[j];
                }
            }
        }
    }
    __syncthreads();
    {
        float4* go = (float4*)(g_min + (size_t)rb * 64 * HH);
        const float4* si = (const float4*)sMin;
        for (int i = tid; i < 1024; i += 256) go[i] = si[i];
    }
}

// ---------------------------------------------------------------------------
// Phase 2: per-batch sequential scan, fp16 r, 2-step register prefetch.
// ---------------------------------------------------------------------------
__global__ __launch_bounds__(128) void k_phase2(const float* __restrict__ xa,
                                                const float* __restrict__ Wo,
                                                const float* __restrict__ bo,
                                                const float* __restrict__ Wfc,
                                                const float* __restrict__ bfc,
                                                float* __restrict__ out) {
    const int b = blockIdx.x;
    const int tid = threadIdx.x;
    const int g = tid >> 4, k4 = tid & 15;
    __shared__ float sc[HH];
    __shared__ float sp[8][HH];
    if (tid < HH) sc[tid] = 0.f;
    __syncthreads();

    const __half* rb_ = g_r + (size_t)b * TT * NC;
    const float*  mb  = g_min + (size_t)b * TT * HH;
    const int foff = (g * 8) * HH + k4 * 4;

    uint2 rv[8], rn[8];
#pragma unroll
    for (int i = 0; i < 8; i++) rv[i] = *(const uint2*)(rb_ + foff + i * HH);
#pragma unroll
    for (int i = 0; i < 8; i++) rn[i] = *(const uint2*)(rb_ + NC + foff + i * HH);
    float mn  = (tid < HH) ? mb[tid] : 0.f;
    float mn1 = (tid < HH) ? mb[HH + tid] : 0.f;

    for (int t = 0; t < TT; t++) {
        const int tn2 = (t + 2 < TT) ? t + 2 : TT - 1;
        const __half* pn = rb_ + (size_t)tn2 * NC + foff;
        uint2 rn2[8];
#pragma unroll
        for (int i = 0; i < 8; i++) rn2[i] = *(const uint2*)(pn + i * HH);
        float mn2 = (tid < HH) ? mb[tn2 * HH + tid] : 0.f;

        float4 p = make_float4(0.f, 0.f, 0.f, 0.f);
#pragma unroll
        for (int i = 0; i < 8; i++) {
            float c = sc[g * 8 + i];
            float2 f01 = __half22float2(*(__half2*)&rv[i].x);
            float2 f23 = __half22float2(*(__half2*)&rv[i].y);
            p.x = fmaf(c, f01.x, p.x);
            p.y = fmaf(c, f01.y, p.y);
            p.z = fmaf(c, f23.x, p.z);
            p.w = fmaf(c, f23.y, p.w);
        }
        *(float4*)&sp[g][k4 * 4] = p;
        __syncthreads();
        if (tid < HH) {
            float v = mn;
#pragma unroll
            for (int gg = 0; gg < 8; gg++) v += sp[gg][tid];
            sc[tid] = v;
        }
        __syncthreads();
#pragma unroll
        for (int i = 0; i < 8; i++) { rv[i] = rn[i]; rn[i] = rn2[i]; }
        mn = mn1; mn1 = mn2;
    }

    if (tid < HH) {
        const int k = tid;
        const float* xarow = xa + ((size_t)b * TT + (TT - 1)) * AUX;
        float acc = bo[k];
#pragma unroll
        for (int a = 0; a < AUX; a++) acc = fmaf(xarow[a], Wo[a * HH + k], acc);
        float o = 1.f / (1.f + __expf(-acc));
        float cfin = sc[k];
        out[BB + b * HH + k] = cfin;           // c_final at offset 256
        sp[0][k] = o * cfin * Wfc[k];
    }
    __syncthreads();
    if (tid == 0) {
        float s = bfc[0];
        for (int i = 0; i < HH; i++) s += sp[0][i];
        out[b] = s;                            // out[b, 0]
    }
}

extern "C" void kernel_launch(void* const* d_in, const int* in_sizes, int n_in,
                              void* d_out, int out_size) {
    const float* xm  = (const float*)d_in[0];
    const float* xa  = (const float*)d_in[1];
    const float* Wj  = (const float*)d_in[2];
    const float* bj  = (const float*)d_in[3];
    const float* Wr  = (const float*)d_in[4];
    const float* br  = (const float*)d_in[5];
    const float* Wo  = (const float*)d_in[6];
    const float* bo  = (const float*)d_in[7];
    const float* Wfc = (const float*)d_in[8];
    const float* bfc = (const float*)d_in[9];
    float* out = (float*)d_out;

    static bool attr_done = false;
    if (!attr_done) {
        cudaFuncSetAttribute(k_phase1b, cudaFuncAttributeMaxDynamicSharedMemorySize, 67584);
        attr_done = true;
    }

    k_cvt_xa<<<2048, 256>>>(xa);                           // xa -> fp16
    k_cvt_w <<<512, 256>>>(Wr);                            // Wr -> fp16 transposed
    k_phase1 <<<32768, 256>>>(br);                         // tensor-core GEMM+softmax
    k_phase1b<<<BT / 64, 256, 67584>>>(xa, xm, Wj, bj);    // 1024 blocks
    k_phase2 <<<BB, 128>>>(xa, Wo, bo, Wfc, bfc, out);     // 256 blocks
}